// round 2
// baseline (speedup 1.0000x reference)
#include <cuda_runtime.h>
#include <cuda_bf16.h>
#include <cstdint>

#define NN 8192
#define FD 256
#define HD 64
#define HE 80      // padded h_ext columns (64 h + 1 ones + 15 zero)
#define NTC 72     // C columns (64 h-cols + deg at 64 + pad)
#define BM 32
#define BK 64
#define SA_STR 72  // sA row stride (bf16 elems) -> conflict-free ldmatrix
#define SB_STR 88  // sB row stride (bf16 elems) -> conflict-free ldmatrix

// device scratch (static allocation only — no cudaMalloc allowed)
__device__ __align__(16) __nv_bfloat16 g_hext[NN * HE];
__device__ __align__(16) float g_C[NN * NTC];

typedef unsigned int uint;

// ---------------------------------------------------------------------------
// K_h: h = x @ Wt^T + bt  ->  g_hext (bf16, padded to 80 cols; col 64 = 1.0)
// Wt held in registers (each thread owns 64 weights), x rows staged in smem.
// ---------------------------------------------------------------------------
__global__ void __launch_bounds__(256) k_h(const float* __restrict__ x,
                                           const float* __restrict__ Wt,
                                           const float* __restrict__ bt) {
    __shared__ float xs[FD];
    __shared__ float part[FD];
    const int tid = threadIdx.x;
    const int c = tid & 63;        // output column
    const int fc = tid >> 6;       // f-chunk 0..3 (64 f each)

    float w[64];
    const float* wr = Wt + (size_t)c * FD + fc * 64;
#pragma unroll
    for (int i = 0; i < 64; i++) w[i] = wr[i];

    int row = blockIdx.x;
    float xr = x[(size_t)row * FD + tid];
    while (row < NN) {
        xs[tid] = xr;
        __syncthreads();
        int nrow = row + gridDim.x;
        if (nrow < NN) xr = x[(size_t)nrow * FD + tid];  // prefetch next row
        float p = 0.f;
#pragma unroll
        for (int i = 0; i < 64; i++) p += xs[fc * 64 + i] * w[i];
        part[fc * 64 + c] = p;
        __syncthreads();
        if (tid < HD) {
            float hv = part[tid] + part[64 + tid] + part[128 + tid] + part[192 + tid] + bt[tid];
            g_hext[(size_t)row * HE + tid] = __float2bfloat16(hv);
        } else if (tid < HE) {
            g_hext[(size_t)row * HE + tid] = __float2bfloat16(tid == HD ? 1.f : 0.f);
        }
        __syncthreads();
        row = nrow;
    }
}

// ---------------------------------------------------------------------------
// K_mm: C[8192, 72] = adj(bf16 0/1) @ h_ext   via mma.sync m16n8k16 bf16
//  - BM=32 rows/CTA (grid 256 -> all 148 SMs covered, ~2 CTAs/SM), BK=64
//  - warp&1 selects 16-row half; warp>>1 selects n-set ({0..3,8} vs {4..7})
//  - adj int32 loaded to regs, converted to bf16 on store to smem
//  - 1-deep register prefetch: next tile's LDGs issued before current mma
//  - column 64 of h_ext is 1.0 -> C[:,64] = deg (exact in fp32 accum)
// ---------------------------------------------------------------------------
__global__ void __launch_bounds__(128) k_adj_mm(const int* __restrict__ adj) {
    __shared__ __align__(16) __nv_bfloat16 sA[BM * SA_STR];  // [m][k]
    __shared__ __align__(16) __nv_bfloat16 sB[BK * SB_STR];  // [k][n]
    const int tid = threadIdx.x;
    const int warp = tid >> 5, lane = tid & 31;
    const int rowBase = blockIdx.x * BM;
    const int ra = tid >> 2;            // adj row owned by this thread (4 thr/row)
    const int kOff = (tid & 3) * 16;    // 16-int chunk within the 64-int tile
    const int* adjp = adj + (size_t)(rowBase + ra) * NN + kOff;

    const int nset = warp >> 1;         // 0: tiles {0,1,2,3,8}   1: tiles {4,5,6,7}
    const int mrow = (warp & 1) * 16;   // row half within the 32-row tile

    float acc[5][4];
#pragma unroll
    for (int i = 0; i < 5; i++) { acc[i][0] = acc[i][1] = acc[i][2] = acc[i][3] = 0.f; }

    int4 rA[4];
    uint4 rB[5];

    // prefetch tile 0
    {
        const int4* ap = (const int4*)adjp;
#pragma unroll
        for (int q = 0; q < 4; q++) rA[q] = ap[q];
#pragma unroll
        for (int s = 0; s < 5; s++) {
            int i = tid + s * 128;
            int r = i / 10, c8 = i % 10;
            rB[s] = *(const uint4*)&g_hext[(size_t)r * HE + c8 * 8];
        }
    }

    const int NIT = NN / BK;  // 128
    for (int kt = 0; kt < NIT; ++kt) {
        // regs -> smem (convert adj int32 {0,1} -> bf16 {0,1.0})
        {
            uint* sAu = (uint*)sA;
#pragma unroll
            for (int q = 0; q < 4; q++) {
                uint lo = (rA[q].x ? 0x3F80u : 0u) | (rA[q].y ? 0x3F800000u : 0u);
                uint hi = (rA[q].z ? 0x3F80u : 0u) | (rA[q].w ? 0x3F800000u : 0u);
                int idx = (ra * SA_STR + kOff + q * 4) >> 1;
                sAu[idx] = lo;
                sAu[idx + 1] = hi;
            }
#pragma unroll
            for (int s = 0; s < 5; s++) {
                int i = tid + s * 128;
                int r = i / 10, c8 = i % 10;
                *(uint4*)&sB[r * SB_STR + c8 * 8] = rB[s];
            }
        }
        __syncthreads();
        // prefetch next tile while mma runs
        if (kt + 1 < NIT) {
            const int4* ap = (const int4*)(adjp + (size_t)(kt + 1) * BK);
#pragma unroll
            for (int q = 0; q < 4; q++) rA[q] = ap[q];
#pragma unroll
            for (int s = 0; s < 5; s++) {
                int i = tid + s * 128;
                int r = i / 10, c8 = i % 10;
                rB[s] = *(const uint4*)&g_hext[(size_t)((kt + 1) * BK + r) * HE + c8 * 8];
            }
        }
        // mma over 4 k-steps of 16
#pragma unroll
        for (int ks = 0; ks < 4; ++ks) {
            uint a0, a1, a2, a3;
            {
                uint32_t addr = (uint32_t)__cvta_generic_to_shared(
                    &sA[(mrow + (lane & 15)) * SA_STR + ks * 16 + ((lane >> 4) << 3)]);
                asm volatile("ldmatrix.sync.aligned.m8n8.x4.shared.b16 {%0,%1,%2,%3},[%4];\n"
                             : "=r"(a0), "=r"(a1), "=r"(a2), "=r"(a3) : "r"(addr));
            }
            const int kk = ks * 16 + (lane & 15);
#pragma unroll
            for (int pl = 0; pl < 2; ++pl) {        // local column pairs
                const int p = nset * 2 + pl;        // global pair: cols p*16..p*16+15
                uint b0, b1, b2, b3;
                uint32_t addr = (uint32_t)__cvta_generic_to_shared(
                    &sB[kk * SB_STR + p * 16 + ((lane >> 4) << 3)]);
                asm volatile("ldmatrix.sync.aligned.m8n8.x4.trans.shared.b16 {%0,%1,%2,%3},[%4];\n"
                             : "=r"(b0), "=r"(b1), "=r"(b2), "=r"(b3) : "r"(addr));
                asm volatile("mma.sync.aligned.m16n8k16.row.col.f32.bf16.bf16.f32 "
                             "{%0,%1,%2,%3},{%4,%5,%6,%7},{%8,%9},{%0,%1,%2,%3};\n"
                             : "+f"(acc[pl * 2][0]), "+f"(acc[pl * 2][1]),
                               "+f"(acc[pl * 2][2]), "+f"(acc[pl * 2][3])
                             : "r"(a0), "r"(a1), "r"(a2), "r"(a3), "r"(b0), "r"(b1));
                asm volatile("mma.sync.aligned.m16n8k16.row.col.f32.bf16.bf16.f32 "
                             "{%0,%1,%2,%3},{%4,%5,%6,%7},{%8,%9},{%0,%1,%2,%3};\n"
                             : "+f"(acc[pl * 2 + 1][0]), "+f"(acc[pl * 2 + 1][1]),
                               "+f"(acc[pl * 2 + 1][2]), "+f"(acc[pl * 2 + 1][3])
                             : "r"(a0), "r"(a1), "r"(a2), "r"(a3), "r"(b2), "r"(b3));
            }
            if (nset == 0) {   // n-tile 8: cols 64..71 (col 64 = deg ones-column)
                uint b0, b1;
                uint32_t addr = (uint32_t)__cvta_generic_to_shared(&sB[kk * SB_STR + 64]);
                asm volatile("ldmatrix.sync.aligned.m8n8.x2.trans.shared.b16 {%0,%1},[%2];\n"
                             : "=r"(b0), "=r"(b1) : "r"(addr));
                asm volatile("mma.sync.aligned.m16n8k16.row.col.f32.bf16.bf16.f32 "
                             "{%0,%1,%2,%3},{%4,%5,%6,%7},{%8,%9},{%0,%1,%2,%3};\n"
                             : "+f"(acc[4][0]), "+f"(acc[4][1]), "+f"(acc[4][2]), "+f"(acc[4][3])
                             : "r"(a0), "r"(a1), "r"(a2), "r"(a3), "r"(b0), "r"(b1));
            }
        }
        __syncthreads();
    }

    // store C tile
    const int gr = lane >> 2, gc = (lane & 3) * 2;
    const int ntiles = (nset == 0) ? 5 : 4;
#pragma unroll
    for (int lt = 0; lt < 5; ++lt) {
        if (lt >= ntiles) break;
        const int gt = (nset == 0) ? ((lt < 4) ? lt : 8) : (4 + lt);
        size_t base = (size_t)(rowBase + mrow + gr) * NTC + gt * 8 + gc;
        g_C[base] = acc[lt][0];
        g_C[base + 1] = acc[lt][1];
        g_C[base + (size_t)8 * NTC] = acc[lt][2];
        g_C[base + (size_t)8 * NTC + 1] = acc[lt][3];
    }
}

// ---------------------------------------------------------------------------
// K_epi: neighbor = C[:, :64]/deg; tf = neighbor @ Wp^T + bp;
//        y = x + tf; LayerNorm(y) -> out.   One block per row.
// ---------------------------------------------------------------------------
__global__ void __launch_bounds__(256) k_epi(const float* __restrict__ x,
                                             const float* __restrict__ Wp,
                                             const float* __restrict__ bp,
                                             const float* __restrict__ gamma,
                                             const float* __restrict__ beta,
                                             float* __restrict__ out) {
    __shared__ float nb[HD];
    __shared__ float red[16];
    const int row = blockIdx.x, t = threadIdx.x;
    if (t < HD) {
        float deg = g_C[(size_t)row * NTC + HD];
        nb[t] = (deg > 0.5f) ? g_C[(size_t)row * NTC + t] / deg : 0.f;
    }
    __syncthreads();

    float tf = bp[t];
    const float4* wp4 = (const float4*)(Wp + (size_t)t * HD);
#pragma unroll
    for (int q = 0; q < 16; q++) {
        float4 wv = wp4[q];
        tf += nb[4 * q + 0] * wv.x + nb[4 * q + 1] * wv.y +
              nb[4 * q + 2] * wv.z + nb[4 * q + 3] * wv.w;
    }
    float y = x[(size_t)row * FD + t] + tf;

    float s = y, sq = y * y;
#pragma unroll
    for (int o = 16; o > 0; o >>= 1) {
        s += __shfl_xor_sync(0xffffffffu, s, o);
        sq += __shfl_xor_sync(0xffffffffu, sq, o);
    }
    if ((t & 31) == 0) { red[t >> 5] = s; red[8 + (t >> 5)] = sq; }
    __syncthreads();
    float ts = 0.f, tq = 0.f;
#pragma unroll
    for (int w = 0; w < 8; w++) { ts += red[w]; tq += red[8 + w]; }
    float mu = ts * (1.f / FD);
    float var = tq * (1.f / FD) - mu * mu;
    float rs = rsqrtf(var + 1e-5f);
    out[(size_t)row * FD + t] = gamma[t] * (y - mu) * rs + beta[t];
}

// ---------------------------------------------------------------------------
extern "C" void kernel_launch(void* const* d_in, const int* in_sizes, int n_in,
                              void* d_out, int out_size) {
    const float* x     = (const float*)d_in[0];
    const int*   adj   = (const int*)d_in[1];
    const float* Wt    = (const float*)d_in[2];
    const float* bt    = (const float*)d_in[3];
    // d_in[4] (Wa), d_in[5] (ba): mathematically irrelevant — softmax over
    // row-constant scores collapses to 1/deg regardless of s.
    const float* Wp    = (const float*)d_in[6];
    const float* bp    = (const float*)d_in[7];
    const float* gamma = (const float*)d_in[8];
    const float* beta  = (const float*)d_in[9];
    float* out = (float*)d_out;

    k_h<<<512, 256>>>(x, Wt, bt);
    k_adj_mm<<<NN / BM, 128>>>(adj);
    k_epi<<<NN, 256>>>(x, Wp, bp, gamma, beta, out);
}

// round 3
// speedup vs baseline: 2.1344x; 2.1344x over previous
#include <cuda_runtime.h>
#include <cuda_bf16.h>
#include <cstdint>

#define NN 8192
#define FD 256
#define HD 64
#define HE 80      // padded h_ext columns (64 h + 1 ones + 15 zero)
#define NTC 72     // C columns (64 h-cols + deg at 64 + pad)
#define BM 64
#define BK 64
#define NIT (NN / BK)          // 128 k-tiles
#define STAGES 4
#define RA_STR 68              // ints per rawA row (pad: conflict-free LDS)
#define RA_TILE (BM * RA_STR)  // 4352 ints  = 17408 B
#define SB_STR 88              // bf16 per sB row (conflict-free ldmatrix)
#define SB_TILE (BK * SB_STR)  // 5632 bf16  = 11264 B
#define SMEM_MM (STAGES * (RA_TILE * 4 + SB_TILE * 2))  // 114688 B

// device scratch (static allocation only — no cudaMalloc allowed)
__device__ __align__(16) __nv_bfloat16 g_hext[NN * HE];
__device__ __align__(16) float g_C[NN * NTC];

typedef unsigned int uint;

__device__ __forceinline__ void cpa16(void* dst, const void* src) {
    uint32_t d = (uint32_t)__cvta_generic_to_shared(dst);
    asm volatile("cp.async.cg.shared.global [%0], [%1], 16;\n" :: "r"(d), "l"(src));
}

// ---------------------------------------------------------------------------
// K_h: h = x @ Wt^T + bt  ->  g_hext (bf16, 80 cols; col 64 = 1.0, rest 0)
// 16-row batches; Wt in registers; 2 syncs per 16 rows.
// ---------------------------------------------------------------------------
__global__ void __launch_bounds__(256) k_h(const float* __restrict__ x,
                                           const float* __restrict__ Wt,
                                           const float* __restrict__ bt) {
    __shared__ __align__(16) float xs[16][FD];      // 16 KB
    __shared__ float part[4][16][64];               // 16 KB
    const int tid = threadIdx.x;
    const int c = tid & 63;        // output column
    const int fc = tid >> 6;       // f-chunk 0..3

    float w[64];
    {
        const float4* wr = (const float4*)(Wt + (size_t)c * FD + fc * 64);
#pragma unroll
        for (int j = 0; j < 16; j++) {
            float4 v = wr[j];
            w[4 * j] = v.x; w[4 * j + 1] = v.y; w[4 * j + 2] = v.z; w[4 * j + 3] = v.w;
        }
    }

    const int r0 = blockIdx.x * 16;   // grid 512 covers 8192 exactly
#pragma unroll 4
    for (int r = 0; r < 16; r++) xs[r][tid] = x[(size_t)(r0 + r) * FD + tid];
    __syncthreads();

#pragma unroll
    for (int r = 0; r < 16; r++) {
        const float4* xv = (const float4*)(&xs[r][fc * 64]);
        float p = 0.f;
#pragma unroll
        for (int j = 0; j < 16; j++) {
            float4 v = xv[j];
            p += v.x * w[4 * j] + v.y * w[4 * j + 1] + v.z * w[4 * j + 2] + v.w * w[4 * j + 3];
        }
        part[fc][r][c] = p;
    }
    __syncthreads();

#pragma unroll
    for (int j = 0; j < 4; j++) {
        int i = tid + j * 256;
        int r = i >> 6, cc = i & 63;
        float hv = part[0][r][cc] + part[1][r][cc] + part[2][r][cc] + part[3][r][cc] + bt[cc];
        g_hext[(size_t)(r0 + r) * HE + cc] = __float2bfloat16(hv);
    }
    {   // pad cols 64..79 (col 64 = ones for deg)
        int r = tid >> 4, cc = 64 + (tid & 15);
        g_hext[(size_t)(r0 + r) * HE + cc] = __float2bfloat16(cc == HD ? 1.f : 0.f);
    }
}

// ---------------------------------------------------------------------------
// K_mm: C[8192, 72] = adj(0/1 -> bf16) @ h_ext   via mma.sync m16n8k16
//  - BM=64, 256 thr, grid 128; 4-stage cp.async pipeline (adj raw int32 + B)
//  - A fragments built in registers from raw ints (2 IMAD per bf16x2 pack)
//  - col 64 of h_ext = 1.0 -> C[:,64] = deg (exact fp32 accum)
// ---------------------------------------------------------------------------
__device__ __forceinline__ void mm_load_tile(const int* __restrict__ adj,
                                             int* rawA, __nv_bfloat16* sB,
                                             int rowBase, int kt, int tid) {
    const int* src = adj + (size_t)rowBase * NN + kt * BK;
#pragma unroll
    for (int j = 0; j < 4; j++) {
        int i = tid + j * 256;          // 1024 chunks of 16B (adj 64x64 int)
        int r = i >> 4, cc = i & 15;
        cpa16(rawA + r * RA_STR + cc * 4, src + (size_t)r * NN + cc * 4);
    }
#pragma unroll
    for (int j = 0; j < 3; j++) {
        int i = tid + j * 256;          // 640 chunks of 16B (h_ext 64x80 bf16)
        if (i < 640) {
            int r = i / 10, cc = i % 10;
            cpa16(sB + r * SB_STR + cc * 8, g_hext + (size_t)(kt * BK + r) * HE + cc * 8);
        }
    }
    asm volatile("cp.async.commit_group;\n");
}

__global__ void __launch_bounds__(256) k_adj_mm(const int* __restrict__ adj) {
    extern __shared__ __align__(16) char dyn[];
    int* rawA0 = (int*)dyn;                                        // [STAGES][RA_TILE]
    __nv_bfloat16* sB0 = (__nv_bfloat16*)(dyn + STAGES * RA_TILE * 4);  // [STAGES][SB_TILE]

    const int tid = threadIdx.x;
    const int warp = tid >> 5, lane = tid & 31;
    const int rowBase = blockIdx.x * BM;
    const int mrow = (warp & 3) * 16;     // 4 row-groups of 16
    const int nset = warp >> 2;           // 0: tiles 0-4 (cols 0-39), 1: tiles 5-8 (40-71)

    float acc[5][4];
#pragma unroll
    for (int i = 0; i < 5; i++) { acc[i][0] = acc[i][1] = acc[i][2] = acc[i][3] = 0.f; }

    // prologue: stages 0..2
#pragma unroll
    for (int s = 0; s < STAGES - 1; s++)
        mm_load_tile(adj, rawA0 + s * RA_TILE, sB0 + s * SB_TILE, rowBase, s, tid);

    const int fr = lane >> 2;             // fragment row within 8
    const int fcol = (lane & 3) * 2;      // fragment col pair base

    for (int kt = 0; kt < NIT; ++kt) {
        asm volatile("cp.async.wait_group %0;\n" :: "n"(STAGES - 2));
        __syncthreads();

        if (kt + STAGES - 1 < NIT) {
            int s = (kt + STAGES - 1) & (STAGES - 1);
            mm_load_tile(adj, rawA0 + s * RA_TILE, sB0 + s * SB_TILE,
                         rowBase, kt + STAGES - 1, tid);
        }

        const int* rawA = rawA0 + (kt & (STAGES - 1)) * RA_TILE;
        const __nv_bfloat16* sB = sB0 + (kt & (STAGES - 1)) * SB_TILE;

#pragma unroll
        for (int ks = 0; ks < 4; ++ks) {
            // A fragments straight from raw int32 smem
            const int r0 = mrow + fr;
            const int c0 = ks * 16 + fcol;
            int2 p00 = *(const int2*)&rawA[r0 * RA_STR + c0];
            int2 p10 = *(const int2*)&rawA[(r0 + 8) * RA_STR + c0];
            int2 p01 = *(const int2*)&rawA[r0 * RA_STR + c0 + 8];
            int2 p11 = *(const int2*)&rawA[(r0 + 8) * RA_STR + c0 + 8];
            uint a0 = (uint)p00.x * 0x3F80u + (uint)p00.y * 0x3F800000u;
            uint a1 = (uint)p10.x * 0x3F80u + (uint)p10.y * 0x3F800000u;
            uint a2 = (uint)p01.x * 0x3F80u + (uint)p01.y * 0x3F800000u;
            uint a3 = (uint)p11.x * 0x3F80u + (uint)p11.y * 0x3F800000u;

            const int kk = ks * 16 + (lane & 15);
#pragma unroll
            for (int pl = 0; pl < 2; ++pl) {          // two x4 ldmatrix per nset
                const int colb = nset * 40 + pl * 16; // nset0: 0,16  nset1: 40,56
                uint b0, b1, b2, b3;
                uint32_t addr = (uint32_t)__cvta_generic_to_shared(
                    &sB[kk * SB_STR + colb + ((lane >> 4) << 3)]);
                asm volatile("ldmatrix.sync.aligned.m8n8.x4.trans.shared.b16 {%0,%1,%2,%3},[%4];\n"
                             : "=r"(b0), "=r"(b1), "=r"(b2), "=r"(b3) : "r"(addr));
                asm volatile("mma.sync.aligned.m16n8k16.row.col.f32.bf16.bf16.f32 "
                             "{%0,%1,%2,%3},{%4,%5,%6,%7},{%8,%9},{%0,%1,%2,%3};\n"
                             : "+f"(acc[pl * 2][0]), "+f"(acc[pl * 2][1]),
                               "+f"(acc[pl * 2][2]), "+f"(acc[pl * 2][3])
                             : "r"(a0), "r"(a1), "r"(a2), "r"(a3), "r"(b0), "r"(b1));
                asm volatile("mma.sync.aligned.m16n8k16.row.col.f32.bf16.bf16.f32 "
                             "{%0,%1,%2,%3},{%4,%5,%6,%7},{%8,%9},{%0,%1,%2,%3};\n"
                             : "+f"(acc[pl * 2 + 1][0]), "+f"(acc[pl * 2 + 1][1]),
                               "+f"(acc[pl * 2 + 1][2]), "+f"(acc[pl * 2 + 1][3])
                             : "r"(a0), "r"(a1), "r"(a2), "r"(a3), "r"(b2), "r"(b3));
            }
            if (nset == 0) {   // tile 4: cols 32-39
                uint b0, b1;
                uint32_t addr = (uint32_t)__cvta_generic_to_shared(&sB[kk * SB_STR + 32]);
                asm volatile("ldmatrix.sync.aligned.m8n8.x2.trans.shared.b16 {%0,%1},[%2];\n"
                             : "=r"(b0), "=r"(b1) : "r"(addr));
                asm volatile("mma.sync.aligned.m16n8k16.row.col.f32.bf16.bf16.f32 "
                             "{%0,%1,%2,%3},{%4,%5,%6,%7},{%8,%9},{%0,%1,%2,%3};\n"
                             : "+f"(acc[4][0]), "+f"(acc[4][1]), "+f"(acc[4][2]), "+f"(acc[4][3])
                             : "r"(a0), "r"(a1), "r"(a2), "r"(a3), "r"(b0), "r"(b1));
            }
        }
        __syncthreads();
    }

    // store C tile
    const int gr = lane >> 2, gc = (lane & 3) * 2;
    const int ntiles = (nset == 0) ? 5 : 4;
#pragma unroll
    for (int lt = 0; lt < 5; ++lt) {
        if (lt >= ntiles) break;
        const int gt = (nset == 0) ? lt : (5 + lt);
        size_t base = (size_t)(rowBase + mrow + gr) * NTC + gt * 8 + gc;
        g_C[base] = acc[lt][0];
        g_C[base + 1] = acc[lt][1];
        g_C[base + (size_t)8 * NTC] = acc[lt][2];
        g_C[base + (size_t)8 * NTC + 1] = acc[lt][3];
    }
}

// ---------------------------------------------------------------------------
// K_epi: 16 rows per CTA.  neighbor = C[:, :64]/deg; tf = neighbor @ Wp^T + bp;
//        y = x + tf; LayerNorm(y) -> out.
// ---------------------------------------------------------------------------
__global__ void __launch_bounds__(256) k_epi(const float* __restrict__ x,
                                             const float* __restrict__ Wp,
                                             const float* __restrict__ bp,
                                             const float* __restrict__ gamma,
                                             const float* __restrict__ beta,
                                             float* __restrict__ out) {
    __shared__ __align__(16) float nb[16][HD];   // 4 KB
    __shared__ float pwS[8][16], pwQ[8][16];
    __shared__ float muS[16], rsS[16];
    const int row0 = blockIdx.x * 16;
    const int t = threadIdx.x;
    const int warp = t >> 5, lane = t & 31;

#pragma unroll
    for (int j = 0; j < 4; j++) {
        int i = t + j * 256;
        int r = i >> 6, cc = i & 63;
        float deg = g_C[(size_t)(row0 + r) * NTC + HD];
        float v = g_C[(size_t)(row0 + r) * NTC + cc];
        nb[r][cc] = (deg > 0.5f) ? v / deg : 0.f;
    }
    __syncthreads();

    float tf[16];
    {
        float b = bp[t];
#pragma unroll
        for (int r = 0; r < 16; r++) tf[r] = b;
    }
    const float4* wp4 = (const float4*)(Wp + (size_t)t * HD);
#pragma unroll
    for (int q = 0; q < 16; q++) {
        float4 w = wp4[q];
#pragma unroll
        for (int r = 0; r < 16; r++) {
            float4 nv = *(const float4*)(&nb[r][q * 4]);
            tf[r] += nv.x * w.x + nv.y * w.y + nv.z * w.z + nv.w * w.w;
        }
    }

    float y[16];
#pragma unroll
    for (int r = 0; r < 16; r++) y[r] = x[(size_t)(row0 + r) * FD + t] + tf[r];

#pragma unroll
    for (int r = 0; r < 16; r++) {
        float s = y[r], q = y[r] * y[r];
#pragma unroll
        for (int o = 16; o > 0; o >>= 1) {
            s += __shfl_xor_sync(0xffffffffu, s, o);
            q += __shfl_xor_sync(0xffffffffu, q, o);
        }
        if (lane == 0) { pwS[warp][r] = s; pwQ[warp][r] = q; }
    }
    __syncthreads();
    if (t < 16) {
        float s = 0.f, q = 0.f;
#pragma unroll
        for (int w = 0; w < 8; w++) { s += pwS[w][t]; q += pwQ[w][t]; }
        float mu = s * (1.f / FD);
        float var = q * (1.f / FD) - mu * mu;
        muS[t] = mu;
        rsS[t] = rsqrtf(var + 1e-5f);
    }
    __syncthreads();

    const float g = gamma[t], b = beta[t];
#pragma unroll
    for (int r = 0; r < 16; r++)
        out[(size_t)(row0 + r) * FD + t] = g * (y[r] - muS[r]) * rsS[r] + b;
}

// ---------------------------------------------------------------------------
extern "C" void kernel_launch(void* const* d_in, const int* in_sizes, int n_in,
                              void* d_out, int out_size) {
    const float* x     = (const float*)d_in[0];
    const int*   adj   = (const int*)d_in[1];
    const float* Wt    = (const float*)d_in[2];
    const float* bt    = (const float*)d_in[3];
    // d_in[4] (Wa), d_in[5] (ba): mathematically irrelevant — softmax over
    // row-constant scores collapses to 1/deg regardless of s.
    const float* Wp    = (const float*)d_in[6];
    const float* bp    = (const float*)d_in[7];
    const float* gamma = (const float*)d_in[8];
    const float* beta  = (const float*)d_in[9];
    float* out = (float*)d_out;

    cudaFuncSetAttribute(k_adj_mm, cudaFuncAttributeMaxDynamicSharedMemorySize, SMEM_MM);
    k_h<<<512, 256>>>(x, Wt, bt);
    k_adj_mm<<<NN / BM, 256, SMEM_MM>>>(adj);
    k_epi<<<NN / 16, 256>>>(x, Wp, bp, gamma, beta, out);
}